// round 1
// baseline (speedup 1.0000x reference)
#include <cuda_runtime.h>

// MemoryModule: B=8,L=12,T=36,D=1024,F=3,C=32
// out[b,c,l,d] = q[b,c,l,d] + sum_t softmax_t(relu(mq))[b,c,l,t] * cmat[b,c,l,t,d]
// Factorizations:
//   mq[c,t] = sum_{f,g} Wm[c,f] Wq[c,g] G[t,f,g] + bm[c]*(Wq[c]·XLsum)
//           + bq[c]*(Wm[c]·XHsum[t]) + D*bm[c]*bq[c]
//   o[c,d]  = sum_f Wc[c,f] * (sum_t att[c,t]*xh[t,d,f]) + bc[c]   (sum att = 1)

#define Bb 8
#define Ll 12
#define Tt 36
#define Dd 1024
#define Ff 3
#define Cc 32
#define BL (Bb * Ll)
#define SPLIT 8

__device__ float g_att[BL * Cc * Tt];

// ---------------------------------------------------------------------------
// Kernel 1: per (b,l) compute G[t,3,3], row sums, scores, softmax -> g_att
// Grid: 96 CTAs x 1024 threads. HBM-bound (streams x_hist once).
// ---------------------------------------------------------------------------
__global__ __launch_bounds__(1024, 1) void k_att(
    const float* __restrict__ xl_g, const float* __restrict__ xh_g,
    const float* __restrict__ Wq, const float* __restrict__ bq,
    const float* __restrict__ Wm, const float* __restrict__ bm)
{
    int bl = blockIdx.x;
    const float* xl = xl_g + (size_t)bl * Dd * Ff;
    const float* xh = xh_g + (size_t)bl * Tt * Dd * Ff;

    __shared__ float s_xl[Dd * Ff];     // 12 KB local features
    __shared__ float s_G[Tt][12];       // G[9] + XHsum[3] per t
    __shared__ float s_XL[3];
    __shared__ float s_mq[Cc][Tt];

    int tid = threadIdx.x, w = tid >> 5, lane = tid & 31;

    for (int i = tid; i < Dd * Ff; i += 1024) s_xl[i] = xl[i];
    __syncthreads();

    // warp w reduces t = w (and w+32 for w<4) over the full D axis
    for (int tt = w; tt < Tt; tt += 32) {
        const float* xp = xh + (size_t)tt * Dd * Ff;
        float G0 = 0, G1 = 0, G2 = 0, G3 = 0, G4 = 0, G5 = 0, G6 = 0, G7 = 0, G8 = 0;
        float XH0 = 0, XH1 = 0, XH2 = 0, XL0 = 0, XL1 = 0, XL2 = 0;
        #pragma unroll 4
        for (int db = 0; db < Dd; db += 32) {
            int d = db + lane;
            float a0 = xp[d * 3 + 0], a1 = xp[d * 3 + 1], a2 = xp[d * 3 + 2];
            float b0 = s_xl[d * 3 + 0], b1 = s_xl[d * 3 + 1], b2 = s_xl[d * 3 + 2];
            G0 = fmaf(a0, b0, G0); G1 = fmaf(a0, b1, G1); G2 = fmaf(a0, b2, G2);
            G3 = fmaf(a1, b0, G3); G4 = fmaf(a1, b1, G4); G5 = fmaf(a1, b2, G5);
            G6 = fmaf(a2, b0, G6); G7 = fmaf(a2, b1, G7); G8 = fmaf(a2, b2, G8);
            XH0 += a0; XH1 += a1; XH2 += a2;
            if (tt == 0) { XL0 += b0; XL1 += b1; XL2 += b2; }
        }
        #pragma unroll
        for (int o = 16; o; o >>= 1) {
            G0 += __shfl_down_sync(~0u, G0, o);
            G1 += __shfl_down_sync(~0u, G1, o);
            G2 += __shfl_down_sync(~0u, G2, o);
            G3 += __shfl_down_sync(~0u, G3, o);
            G4 += __shfl_down_sync(~0u, G4, o);
            G5 += __shfl_down_sync(~0u, G5, o);
            G6 += __shfl_down_sync(~0u, G6, o);
            G7 += __shfl_down_sync(~0u, G7, o);
            G8 += __shfl_down_sync(~0u, G8, o);
            XH0 += __shfl_down_sync(~0u, XH0, o);
            XH1 += __shfl_down_sync(~0u, XH1, o);
            XH2 += __shfl_down_sync(~0u, XH2, o);
            if (tt == 0) {
                XL0 += __shfl_down_sync(~0u, XL0, o);
                XL1 += __shfl_down_sync(~0u, XL1, o);
                XL2 += __shfl_down_sync(~0u, XL2, o);
            }
        }
        if (lane == 0) {
            s_G[tt][0] = G0; s_G[tt][1] = G1; s_G[tt][2] = G2;
            s_G[tt][3] = G3; s_G[tt][4] = G4; s_G[tt][5] = G5;
            s_G[tt][6] = G6; s_G[tt][7] = G7; s_G[tt][8] = G8;
            s_G[tt][9] = XH0; s_G[tt][10] = XH1; s_G[tt][11] = XH2;
            if (tt == 0) { s_XL[0] = XL0; s_XL[1] = XL1; s_XL[2] = XL2; }
        }
    }
    __syncthreads();

    // scores: mq[c,t] via the G factorization, relu applied
    for (int i = tid; i < Cc * Tt; i += 1024) {
        int c = i / Tt, t = i - c * Tt;
        float wm0 = Wm[c * 3 + 0], wm1 = Wm[c * 3 + 1], wm2 = Wm[c * 3 + 2];
        float wq0 = Wq[c * 3 + 0], wq1 = Wq[c * 3 + 1], wq2 = Wq[c * 3 + 2];
        float bmc = bm[c], bqc = bq[c];
        const float* Gp = s_G[t];
        float v = wm0 * (wq0 * Gp[0] + wq1 * Gp[1] + wq2 * Gp[2])
                + wm1 * (wq0 * Gp[3] + wq1 * Gp[4] + wq2 * Gp[5])
                + wm2 * (wq0 * Gp[6] + wq1 * Gp[7] + wq2 * Gp[8])
                + bmc * (wq0 * s_XL[0] + wq1 * s_XL[1] + wq2 * s_XL[2])
                + bqc * (wm0 * Gp[9] + wm1 * Gp[10] + wm2 * Gp[11])
                + (float)Dd * bmc * bqc;
        s_mq[c][t] = fmaxf(v, 0.0f);
    }
    __syncthreads();

    // softmax over t: warp w handles channel c = w
    {
        int c = w;
        float v0 = s_mq[c][lane];                                   // t = lane (<32)
        float v1 = (lane < Tt - 32) ? s_mq[c][lane + 32] : -3.0e38f; // t = lane+32
        float mx = fmaxf(v0, v1);
        #pragma unroll
        for (int o = 16; o; o >>= 1) mx = fmaxf(mx, __shfl_xor_sync(~0u, mx, o));
        float e0 = __expf(v0 - mx);
        float e1 = (lane < Tt - 32) ? __expf(v1 - mx) : 0.0f;
        float s = e0 + e1;
        #pragma unroll
        for (int o = 16; o; o >>= 1) s += __shfl_xor_sync(~0u, s, o);
        float inv = 1.0f / s;
        float* ap = g_att + ((size_t)bl * Cc + c) * Tt;
        ap[lane] = e0 * inv;
        if (lane < Tt - 32) ap[lane + 32] = e1 * inv;
    }
}

// ---------------------------------------------------------------------------
// Kernel 2: out[b,c,l,d] = q + sum_f Wc[c,f]*H_f + bc
// Lane = channel c (att in registers), warp sweeps 32 d's (4 at a time,
// 3x LDG.128 uniform-broadcast per t). Grid: 768 CTAs x 128 threads.
// ---------------------------------------------------------------------------
__global__ __launch_bounds__(128) void k_out(
    const float* __restrict__ xl_g, const float* __restrict__ xh_g,
    const float* __restrict__ Wq, const float* __restrict__ bq,
    const float* __restrict__ Wc, const float* __restrict__ bc,
    float* __restrict__ out)
{
    int blk = blockIdx.x;
    int bl = blk / SPLIT, chunk = blk - bl * SPLIT;
    int b = bl / Ll, l = bl - b * Ll;
    int w = threadIdx.x >> 5, c = threadIdx.x & 31;

    const float* xh = xh_g + (size_t)bl * Tt * Dd * Ff;
    const float* xl = xl_g + (size_t)bl * Dd * Ff;

    float att[Tt];
    {
        const float4* ap = (const float4*)(g_att + ((size_t)bl * Cc + c) * Tt);
        #pragma unroll
        for (int i = 0; i < Tt / 4; i++) {
            float4 v = ap[i];
            att[4 * i + 0] = v.x; att[4 * i + 1] = v.y;
            att[4 * i + 2] = v.z; att[4 * i + 3] = v.w;
        }
    }
    float wc0 = Wc[c * 3 + 0], wc1 = Wc[c * 3 + 1], wc2 = Wc[c * 3 + 2], bcc = bc[c];
    float wq0 = Wq[c * 3 + 0], wq1 = Wq[c * 3 + 1], wq2 = Wq[c * 3 + 2], bqc = bq[c];

    int d0 = chunk * (Dd / SPLIT) + w * 32;
    float* op = out + (((size_t)b * Cc + c) * Ll + l) * Dd;

    for (int g2 = 0; g2 < 32; g2 += 4) {
        int d = d0 + g2;
        float h[12];
        #pragma unroll
        for (int j = 0; j < 12; j++) h[j] = 0.0f;
        #pragma unroll
        for (int t = 0; t < Tt; t++) {
            const float4* p = (const float4*)(xh + ((size_t)t * Dd + d) * Ff);
            float4 A = p[0], Bv = p[1], Cv = p[2];
            float a = att[t];
            h[0] = fmaf(a, A.x, h[0]);  h[1] = fmaf(a, A.y, h[1]);  h[2]  = fmaf(a, A.z,  h[2]);
            h[3] = fmaf(a, A.w, h[3]);  h[4] = fmaf(a, Bv.x, h[4]); h[5]  = fmaf(a, Bv.y, h[5]);
            h[6] = fmaf(a, Bv.z, h[6]); h[7] = fmaf(a, Bv.w, h[7]); h[8]  = fmaf(a, Cv.x, h[8]);
            h[9] = fmaf(a, Cv.y, h[9]); h[10] = fmaf(a, Cv.z, h[10]); h[11] = fmaf(a, Cv.w, h[11]);
        }
        #pragma unroll
        for (int j = 0; j < 4; j++) {
            float ov = fmaf(wc2, h[3 * j + 2], fmaf(wc1, h[3 * j + 1], fmaf(wc0, h[3 * j + 0], bcc)));
            float x0 = xl[(d + j) * 3 + 0], x1 = xl[(d + j) * 3 + 1], x2 = xl[(d + j) * 3 + 2];
            float q = fmaf(wq2, x2, fmaf(wq1, x1, fmaf(wq0, x0, bqc)));
            op[d + j] = q + ov;
        }
    }
}

extern "C" void kernel_launch(void* const* d_in, const int* in_sizes, int n_in,
                              void* d_out, int out_size)
{
    const float* xl = (const float*)d_in[0];
    const float* xh = (const float*)d_in[1];
    const float* Wq = (const float*)d_in[2];
    const float* bq = (const float*)d_in[3];
    const float* Wm = (const float*)d_in[4];
    const float* bm = (const float*)d_in[5];
    const float* Wc = (const float*)d_in[6];
    const float* bc = (const float*)d_in[7];
    float* out = (float*)d_out;

    k_att<<<BL, 1024>>>(xl, xh, Wq, bq, Wm, bm);
    k_out<<<BL * SPLIT, 128>>>(xl, xh, Wq, bq, Wc, bc, out);
}

// round 2
// speedup vs baseline: 1.8000x; 1.8000x over previous
#include <cuda_runtime.h>

// MemoryModule: B=8,L=12,T=36,D=1024,F=3,C=32
//   mq[c,t] = sum_{f,g} Wm[c,f] Wq[c,g] G[t,f,g] + bm[c]*(Wq[c]·XLsum)
//           + bq[c]*(Wm[c]·XHsum[t]) + D*bm[c]*bq[c]
//   o[c,d]  = sum_f Wc[c,f] * (sum_t att[c,t]*xh[t,d,f]) + bc[c]
// k_out v2: smem-staged tile (cp.async) + packed fma.rn.f32x2 accumulation.

#define Bb 8
#define Ll 12
#define Tt 36
#define Dd 1024
#define Ff 3
#define Cc 32
#define BL (Bb * Ll)
#define DC 128
#define CHUNKS (Dd / DC)   // 8

// att duplicated as (a,a) pairs, layout [bl][t][c] for conflict-free LDS.64
__device__ __align__(16) float g_att2[BL * Tt * Cc * 2];

#define FFMA2(d, a, b) \
    asm("fma.rn.f32x2 %0, %1, %2, %0;" : "+l"(d) : "l"(a), "l"(b))

#define CP16(dst, src) \
    asm volatile("cp.async.cg.shared.global [%0], [%1], 16;" :: "r"(dst), "l"(src))

union U2F { unsigned long long u; float2 f; };

// ---------------------------------------------------------------------------
// Kernel 1: per (b,l): G[t,3,3] + row sums -> scores -> softmax -> g_att2
// ---------------------------------------------------------------------------
__global__ __launch_bounds__(1024, 1) void k_att(
    const float* __restrict__ xl_g, const float* __restrict__ xh_g,
    const float* __restrict__ Wq, const float* __restrict__ bq,
    const float* __restrict__ Wm, const float* __restrict__ bm)
{
    int bl = blockIdx.x;
    const float* xl = xl_g + (size_t)bl * Dd * Ff;
    const float* xh = xh_g + (size_t)bl * Tt * Dd * Ff;

    __shared__ float s_xl[Dd * Ff];
    __shared__ float s_G[Tt][12];
    __shared__ float s_XL[3];
    __shared__ float s_mq[Cc][Tt];

    int tid = threadIdx.x, w = tid >> 5, lane = tid & 31;

    for (int i = tid; i < Dd * Ff; i += 1024) s_xl[i] = xl[i];
    __syncthreads();

    for (int tt = w; tt < Tt; tt += 32) {
        const float* xp = xh + (size_t)tt * Dd * Ff;
        float G0 = 0, G1 = 0, G2 = 0, G3 = 0, G4 = 0, G5 = 0, G6 = 0, G7 = 0, G8 = 0;
        float XH0 = 0, XH1 = 0, XH2 = 0, XL0 = 0, XL1 = 0, XL2 = 0;
        #pragma unroll 4
        for (int db = 0; db < Dd; db += 32) {
            int d = db + lane;
            float a0 = xp[d * 3 + 0], a1 = xp[d * 3 + 1], a2 = xp[d * 3 + 2];
            float b0 = s_xl[d * 3 + 0], b1 = s_xl[d * 3 + 1], b2 = s_xl[d * 3 + 2];
            G0 = fmaf(a0, b0, G0); G1 = fmaf(a0, b1, G1); G2 = fmaf(a0, b2, G2);
            G3 = fmaf(a1, b0, G3); G4 = fmaf(a1, b1, G4); G5 = fmaf(a1, b2, G5);
            G6 = fmaf(a2, b0, G6); G7 = fmaf(a2, b1, G7); G8 = fmaf(a2, b2, G8);
            XH0 += a0; XH1 += a1; XH2 += a2;
            if (tt == 0) { XL0 += b0; XL1 += b1; XL2 += b2; }
        }
        #pragma unroll
        for (int o = 16; o; o >>= 1) {
            G0 += __shfl_down_sync(~0u, G0, o);  G1 += __shfl_down_sync(~0u, G1, o);
            G2 += __shfl_down_sync(~0u, G2, o);  G3 += __shfl_down_sync(~0u, G3, o);
            G4 += __shfl_down_sync(~0u, G4, o);  G5 += __shfl_down_sync(~0u, G5, o);
            G6 += __shfl_down_sync(~0u, G6, o);  G7 += __shfl_down_sync(~0u, G7, o);
            G8 += __shfl_down_sync(~0u, G8, o);
            XH0 += __shfl_down_sync(~0u, XH0, o); XH1 += __shfl_down_sync(~0u, XH1, o);
            XH2 += __shfl_down_sync(~0u, XH2, o);
            if (tt == 0) {
                XL0 += __shfl_down_sync(~0u, XL0, o);
                XL1 += __shfl_down_sync(~0u, XL1, o);
                XL2 += __shfl_down_sync(~0u, XL2, o);
            }
        }
        if (lane == 0) {
            s_G[tt][0] = G0; s_G[tt][1] = G1; s_G[tt][2] = G2;
            s_G[tt][3] = G3; s_G[tt][4] = G4; s_G[tt][5] = G5;
            s_G[tt][6] = G6; s_G[tt][7] = G7; s_G[tt][8] = G8;
            s_G[tt][9] = XH0; s_G[tt][10] = XH1; s_G[tt][11] = XH2;
            if (tt == 0) { s_XL[0] = XL0; s_XL[1] = XL1; s_XL[2] = XL2; }
        }
    }
    __syncthreads();

    for (int i = tid; i < Cc * Tt; i += 1024) {
        int c = i / Tt, t = i - c * Tt;
        float wm0 = Wm[c * 3 + 0], wm1 = Wm[c * 3 + 1], wm2 = Wm[c * 3 + 2];
        float wq0 = Wq[c * 3 + 0], wq1 = Wq[c * 3 + 1], wq2 = Wq[c * 3 + 2];
        float bmc = bm[c], bqc = bq[c];
        const float* Gp = s_G[t];
        float v = wm0 * (wq0 * Gp[0] + wq1 * Gp[1] + wq2 * Gp[2])
                + wm1 * (wq0 * Gp[3] + wq1 * Gp[4] + wq2 * Gp[5])
                + wm2 * (wq0 * Gp[6] + wq1 * Gp[7] + wq2 * Gp[8])
                + bmc * (wq0 * s_XL[0] + wq1 * s_XL[1] + wq2 * s_XL[2])
                + bqc * (wm0 * Gp[9] + wm1 * Gp[10] + wm2 * Gp[11])
                + (float)Dd * bmc * bqc;
        s_mq[c][t] = fmaxf(v, 0.0f);
    }
    __syncthreads();

    {
        int c = w;   // warp per channel
        float v0 = s_mq[c][lane];
        float v1 = (lane < Tt - 32) ? s_mq[c][lane + 32] : -3.0e38f;
        float mx = fmaxf(v0, v1);
        #pragma unroll
        for (int o = 16; o; o >>= 1) mx = fmaxf(mx, __shfl_xor_sync(~0u, mx, o));
        float e0 = __expf(v0 - mx);
        float e1 = (lane < Tt - 32) ? __expf(v1 - mx) : 0.0f;
        float s = e0 + e1;
        #pragma unroll
        for (int o = 16; o; o >>= 1) s += __shfl_xor_sync(~0u, s, o);
        float inv = 1.0f / s;
        float2* ap = (float2*)g_att2 + (size_t)bl * Tt * Cc;
        float a0 = e0 * inv;
        ap[lane * Cc + c] = make_float2(a0, a0);             // t = lane
        if (lane < Tt - 32) {
            float a1 = e1 * inv;
            ap[(lane + 32) * Cc + c] = make_float2(a1, a1);  // t = lane+32
        }
    }
}

// ---------------------------------------------------------------------------
// Kernel 2: CTA = (bl, 128-d chunk). Stage tile in smem via cp.async, then
// lane=c accumulates H pairs with FFMA2. Grid 768 x 256 threads.
// smem: tile[36][384] + att2[36][32]f2 + xl[384]  = 66048 B
// ---------------------------------------------------------------------------
#define SM_TILE_F (Tt * DC * Ff)          // 13824 floats
#define SM_ATT_F  (Tt * Cc * 2)           // 2304 floats
#define SM_XL_F   (DC * Ff)               // 384 floats
#define N_CP16    ((SM_TILE_F + SM_ATT_F + SM_XL_F) / 4)   // 4128

__global__ __launch_bounds__(256, 3) void k_out(
    const float* __restrict__ xl_g, const float* __restrict__ xh_g,
    const float* __restrict__ Wq, const float* __restrict__ bq,
    const float* __restrict__ Wc, const float* __restrict__ bc,
    float* __restrict__ out)
{
    extern __shared__ float sm[];
    float* s_tile = sm;
    float* s_att  = sm + SM_TILE_F;
    float* s_xl   = sm + SM_TILE_F + SM_ATT_F;

    int blk = blockIdx.x;
    int bl = blk / CHUNKS, chunk = blk - bl * CHUNKS;
    int b = bl / Ll, l = bl - b * Ll;
    int tid = threadIdx.x;

    const float* xh_bl  = xh_g + (size_t)bl * Tt * Dd * Ff + chunk * DC * Ff;
    const float* att_src = (const float*)g_att2 + (size_t)bl * Tt * Cc * 2;
    const float* xl_src = xl_g + (size_t)bl * Dd * Ff + chunk * DC * Ff;

    // ---- bulk async copy: 66 KB -> smem ----
    for (int i = tid; i < N_CP16; i += 256) {
        const float* src;
        unsigned dst;
        if (i < SM_TILE_F / 4) {
            int row = i / (DC * Ff / 4);              // /96
            int col = (i - row * (DC * Ff / 4)) * 4;
            src = xh_bl + (size_t)row * (Dd * Ff) + col;
            dst = (unsigned)__cvta_generic_to_shared(s_tile + row * (DC * Ff) + col);
        } else if (i < (SM_TILE_F + SM_ATT_F) / 4) {
            int j = (i - SM_TILE_F / 4) * 4;
            src = att_src + j;
            dst = (unsigned)__cvta_generic_to_shared(s_att + j);
        } else {
            int j = (i - (SM_TILE_F + SM_ATT_F) / 4) * 4;
            src = xl_src + j;
            dst = (unsigned)__cvta_generic_to_shared(s_xl + j);
        }
        CP16(dst, src);
    }
    asm volatile("cp.async.commit_group;");
    asm volatile("cp.async.wait_group 0;");
    __syncthreads();

    // ---- main accumulation: lane = channel, warp covers 16 d ----
    int wid = tid >> 5, c = tid & 31;
    int dw = wid * 16;

    unsigned long long H[24];
    #pragma unroll
    for (int k = 0; k < 24; k++) H[k] = 0ull;   // bit pattern 0 == (0.f,0.f)

    const unsigned long long* ap = (const unsigned long long*)s_att + c;
    const float* tp = s_tile + dw * Ff;

    #pragma unroll 4
    for (int t = 0; t < Tt; t++) {
        unsigned long long av = ap[t * Cc];
        const ulonglong2* p = (const ulonglong2*)(tp + t * (DC * Ff));
        #pragma unroll
        for (int g = 0; g < 4; g++) {
            ulonglong2 x0 = p[3 * g + 0];
            ulonglong2 x1 = p[3 * g + 1];
            ulonglong2 x2 = p[3 * g + 2];
            FFMA2(H[6 * g + 0], x0.x, av);
            FFMA2(H[6 * g + 1], x0.y, av);
            FFMA2(H[6 * g + 2], x1.x, av);
            FFMA2(H[6 * g + 3], x1.y, av);
            FFMA2(H[6 * g + 4], x2.x, av);
            FFMA2(H[6 * g + 5], x2.y, av);
        }
    }

    // ---- epilogue: combine with Wc / q, write float4 ----
    float wc0 = Wc[c * 3 + 0], wc1 = Wc[c * 3 + 1], wc2 = Wc[c * 3 + 2], bcc = bc[c];
    float wq0 = Wq[c * 3 + 0], wq1 = Wq[c * 3 + 1], wq2 = Wq[c * 3 + 2], bqc = bq[c];

    float* op = out + (((size_t)b * Cc + c) * Ll + l) * Dd + chunk * DC + dw;

    #pragma unroll
    for (int g = 0; g < 4; g++) {
        U2F k0, k1, k2, k3, k4, k5;
        k0.u = H[6 * g + 0]; k1.u = H[6 * g + 1]; k2.u = H[6 * g + 2];
        k3.u = H[6 * g + 3]; k4.u = H[6 * g + 4]; k5.u = H[6 * g + 5];
        // pair layout: (d0f0,d0f1)(d0f2,d1f0)(d1f1,d1f2)(d2f0,d2f1)(d2f2,d3f0)(d3f1,d3f2)
        float ov0 = fmaf(wc2, k1.f.x, fmaf(wc1, k0.f.y, fmaf(wc0, k0.f.x, bcc)));
        float ov1 = fmaf(wc2, k2.f.y, fmaf(wc1, k2.f.x, fmaf(wc0, k1.f.y, bcc)));
        float ov2 = fmaf(wc2, k4.f.x, fmaf(wc1, k3.f.y, fmaf(wc0, k3.f.x, bcc)));
        float ov3 = fmaf(wc2, k5.f.y, fmaf(wc1, k5.f.x, fmaf(wc0, k4.f.y, bcc)));

        const float* xp = s_xl + (dw + 4 * g) * Ff;
        float q0 = fmaf(wq2, xp[2],  fmaf(wq1, xp[1],  fmaf(wq0, xp[0], bqc)));
        float q1 = fmaf(wq2, xp[5],  fmaf(wq1, xp[4],  fmaf(wq0, xp[3], bqc)));
        float q2 = fmaf(wq2, xp[8],  fmaf(wq1, xp[7],  fmaf(wq0, xp[6], bqc)));
        float q3 = fmaf(wq2, xp[11], fmaf(wq1, xp[10], fmaf(wq0, xp[9], bqc)));

        float4 res = make_float4(q0 + ov0, q1 + ov1, q2 + ov2, q3 + ov3);
        *(float4*)(op + 4 * g) = res;
    }
}

extern "C" void kernel_launch(void* const* d_in, const int* in_sizes, int n_in,
                              void* d_out, int out_size)
{
    const float* xl = (const float*)d_in[0];
    const float* xh = (const float*)d_in[1];
    const float* Wq = (const float*)d_in[2];
    const float* bq = (const float*)d_in[3];
    const float* Wm = (const float*)d_in[4];
    const float* bm = (const float*)d_in[5];
    const float* Wc = (const float*)d_in[6];
    const float* bc = (const float*)d_in[7];
    float* out = (float*)d_out;

    static int smem_set = 0;
    if (!smem_set) {
        cudaFuncSetAttribute(k_out, cudaFuncAttributeMaxDynamicSharedMemorySize,
                             (SM_TILE_F + SM_ATT_F + SM_XL_F) * 4);
        smem_set = 1;
    }

    k_att<<<BL, 1024>>>(xl, xh, Wq, bq, Wm, bm);
    k_out<<<BL * CHUNKS, 256, (SM_TILE_F + SM_ATT_F + SM_XL_F) * 4>>>(
        xl, xh, Wq, bq, Wc, bc, out);
}

// round 3
// speedup vs baseline: 1.8085x; 1.0047x over previous
#include <cuda_runtime.h>

// MemoryModule: B=8,L=12,T=36,D=1024,F=3,C=32
//   mq[c,t] = sum_{f,g} Wm[c,f] Wq[c,g] G[t,f,g] + bm[c]*(Wq[c]·XLsum)
//           + bq[c]*(Wm[c]·XHsum[t]) + D*bm[c]*bq[c]
//   o[c,d]  = sum_f Wc[c,f] * (sum_t att[c,t]*xh[t,d,f]) + bc[c]
// v3: k_gram (bulk cp.async G-reduction) + k_score (softmax) + k_out DC=64.

#define Bb 8
#define Ll 12
#define Tt 36
#define Dd 1024
#define Ff 3
#define Cc 32
#define BL (Bb * Ll)
#define DF (Dd * Ff)        // 3072
#define DC 64
#define CHUNKS (Dd / DC)    // 16
#define TG 6                // t's per k_gram CTA

__device__ __align__(16) float g_att2[BL * Tt * Cc * 2]; // (a,a) pairs, [bl][t][c]
__device__ float g_G[BL * Tt * 12];                       // G[9] + XHsum[3]

#define FFMA2(d, a, b) \
    asm("fma.rn.f32x2 %0, %1, %2, %0;" : "+l"(d) : "l"(a), "l"(b))

#define CP16(dst, src) \
    asm volatile("cp.async.cg.shared.global [%0], [%1], 16;" :: "r"(dst), "l"(src))

union U2F { unsigned long long u; float2 f; };

// ---------------------------------------------------------------------------
// k_gram: CTA = (tg, bl). Bulk-stage 6 xh rows (72KB contiguous) + xl (12KB),
// then warps 0..5 reduce G[t,3,3] + XHsum[t] from smem. Grid (6,96) x 256.
// ---------------------------------------------------------------------------
#define GRAM_SMEM_F (TG * DF + DF)          // 21504 floats = 84 KB

__global__ __launch_bounds__(256, 2) void k_gram(
    const float* __restrict__ xh_g, const float* __restrict__ xl_g)
{
    extern __shared__ float sm[];
    float* s_xh = sm;
    float* s_xl = sm + TG * DF;

    int tg = blockIdx.x, bl = blockIdx.y;
    int tid = threadIdx.x, w = tid >> 5, lane = tid & 31;

    const float* xh_src = xh_g + ((size_t)bl * Tt + tg * TG) * DF;
    const float* xl_src = xl_g + (size_t)bl * DF;

    for (int i = tid; i < GRAM_SMEM_F / 4; i += 256) {
        const float* src;
        unsigned dst;
        if (i < TG * DF / 4) {                       // contiguous 72KB slab
            src = xh_src + i * 4;
            dst = (unsigned)__cvta_generic_to_shared(s_xh + i * 4);
        } else {
            int j = (i - TG * DF / 4) * 4;
            src = xl_src + j;
            dst = (unsigned)__cvta_generic_to_shared(s_xl + j);
        }
        CP16(dst, src);
    }
    asm volatile("cp.async.commit_group;");
    asm volatile("cp.async.wait_group 0;");
    __syncthreads();

    if (w < TG) {
        const float* xp = s_xh + w * DF;
        float G0 = 0, G1 = 0, G2 = 0, G3 = 0, G4 = 0, G5 = 0, G6 = 0, G7 = 0, G8 = 0;
        float XH0 = 0, XH1 = 0, XH2 = 0;
        #pragma unroll 4
        for (int db = 0; db < Dd; db += 32) {
            int d = db + lane;
            float a0 = xp[d * 3 + 0], a1 = xp[d * 3 + 1], a2 = xp[d * 3 + 2];
            float b0 = s_xl[d * 3 + 0], b1 = s_xl[d * 3 + 1], b2 = s_xl[d * 3 + 2];
            G0 = fmaf(a0, b0, G0); G1 = fmaf(a0, b1, G1); G2 = fmaf(a0, b2, G2);
            G3 = fmaf(a1, b0, G3); G4 = fmaf(a1, b1, G4); G5 = fmaf(a1, b2, G5);
            G6 = fmaf(a2, b0, G6); G7 = fmaf(a2, b1, G7); G8 = fmaf(a2, b2, G8);
            XH0 += a0; XH1 += a1; XH2 += a2;
        }
        #pragma unroll
        for (int o = 16; o; o >>= 1) {
            G0 += __shfl_down_sync(~0u, G0, o);  G1 += __shfl_down_sync(~0u, G1, o);
            G2 += __shfl_down_sync(~0u, G2, o);  G3 += __shfl_down_sync(~0u, G3, o);
            G4 += __shfl_down_sync(~0u, G4, o);  G5 += __shfl_down_sync(~0u, G5, o);
            G6 += __shfl_down_sync(~0u, G6, o);  G7 += __shfl_down_sync(~0u, G7, o);
            G8 += __shfl_down_sync(~0u, G8, o);
            XH0 += __shfl_down_sync(~0u, XH0, o); XH1 += __shfl_down_sync(~0u, XH1, o);
            XH2 += __shfl_down_sync(~0u, XH2, o);
        }
        if (lane == 0) {
            float* gp = g_G + ((size_t)bl * Tt + tg * TG + w) * 12;
            gp[0] = G0; gp[1] = G1; gp[2] = G2; gp[3] = G3; gp[4] = G4;
            gp[5] = G5; gp[6] = G6; gp[7] = G7; gp[8] = G8;
            gp[9] = XH0; gp[10] = XH1; gp[11] = XH2;
        }
    }
}

// ---------------------------------------------------------------------------
// k_score: per bl: XLsum + scores + softmax -> g_att2. Grid 96 x 256.
// ---------------------------------------------------------------------------
__global__ __launch_bounds__(256) void k_score(
    const float* __restrict__ xl_g,
    const float* __restrict__ Wq, const float* __restrict__ bq,
    const float* __restrict__ Wm, const float* __restrict__ bm)
{
    __shared__ float s_G[Tt][12];
    __shared__ float s_mq[Cc][Tt];
    __shared__ float s_XL[3];

    int bl = blockIdx.x;
    int tid = threadIdx.x, w = tid >> 5, lane = tid & 31;

    if (tid < 3) s_XL[tid] = 0.0f;
    for (int i = tid; i < Tt * 12; i += 256)
        ((float*)s_G)[i] = g_G[(size_t)bl * Tt * 12 + i];

    // XLsum over D (warp-reduce, then smem atomic)
    {
        const float* xl = xl_g + (size_t)bl * DF;
        float x0 = 0, x1 = 0, x2 = 0;
        for (int d = tid; d < Dd; d += 256) {
            x0 += xl[d * 3 + 0]; x1 += xl[d * 3 + 1]; x2 += xl[d * 3 + 2];
        }
        #pragma unroll
        for (int o = 16; o; o >>= 1) {
            x0 += __shfl_down_sync(~0u, x0, o);
            x1 += __shfl_down_sync(~0u, x1, o);
            x2 += __shfl_down_sync(~0u, x2, o);
        }
        __syncthreads();   // s_XL zero + s_G visible
        if (lane == 0) {
            atomicAdd(&s_XL[0], x0); atomicAdd(&s_XL[1], x1); atomicAdd(&s_XL[2], x2);
        }
    }
    __syncthreads();

    for (int i = tid; i < Cc * Tt; i += 256) {
        int c = i / Tt, t = i - c * Tt;
        float wm0 = Wm[c * 3 + 0], wm1 = Wm[c * 3 + 1], wm2 = Wm[c * 3 + 2];
        float wq0 = Wq[c * 3 + 0], wq1 = Wq[c * 3 + 1], wq2 = Wq[c * 3 + 2];
        float bmc = bm[c], bqc = bq[c];
        const float* Gp = s_G[t];
        float v = wm0 * (wq0 * Gp[0] + wq1 * Gp[1] + wq2 * Gp[2])
                + wm1 * (wq0 * Gp[3] + wq1 * Gp[4] + wq2 * Gp[5])
                + wm2 * (wq0 * Gp[6] + wq1 * Gp[7] + wq2 * Gp[8])
                + bmc * (wq0 * s_XL[0] + wq1 * s_XL[1] + wq2 * s_XL[2])
                + bqc * (wm0 * Gp[9] + wm1 * Gp[10] + wm2 * Gp[11])
                + (float)Dd * bmc * bqc;
        s_mq[c][t] = fmaxf(v, 0.0f);
    }
    __syncthreads();

    #pragma unroll
    for (int k = 0; k < 4; k++) {
        int c = w + 8 * k;
        float v0 = s_mq[c][lane];
        float v1 = (lane < Tt - 32) ? s_mq[c][lane + 32] : -3.0e38f;
        float mx = fmaxf(v0, v1);
        #pragma unroll
        for (int o = 16; o; o >>= 1) mx = fmaxf(mx, __shfl_xor_sync(~0u, mx, o));
        float e0 = __expf(v0 - mx);
        float e1 = (lane < Tt - 32) ? __expf(v1 - mx) : 0.0f;
        float s = e0 + e1;
        #pragma unroll
        for (int o = 16; o; o >>= 1) s += __shfl_xor_sync(~0u, s, o);
        float inv = 1.0f / s;
        float2* ap = (float2*)g_att2 + (size_t)bl * Tt * Cc;
        float a0 = e0 * inv;
        ap[lane * Cc + c] = make_float2(a0, a0);
        if (lane < Tt - 32) {
            float a1 = e1 * inv;
            ap[(lane + 32) * Cc + c] = make_float2(a1, a1);
        }
    }
}

// ---------------------------------------------------------------------------
// k_out: CTA = (bl, 64-d chunk). 37.6KB smem -> ~5 CTAs/SM. Lane = channel,
// warp covers 8 d. FFMA2 accumulation. Grid 1536 x 256.
// ---------------------------------------------------------------------------
#define SM_TILE_F (Tt * DC * Ff)          // 6912 floats
#define SM_ATT_F  (Tt * Cc * 2)           // 2304 floats
#define SM_XL_F   (DC * Ff)               // 192 floats
#define N_CP16    ((SM_TILE_F + SM_ATT_F + SM_XL_F) / 4)   // 2352

__global__ __launch_bounds__(256, 5) void k_out(
    const float* __restrict__ xl_g, const float* __restrict__ xh_g,
    const float* __restrict__ Wq, const float* __restrict__ bq,
    const float* __restrict__ Wc, const float* __restrict__ bc,
    float* __restrict__ out)
{
    extern __shared__ float sm[];
    float* s_tile = sm;
    float* s_att  = sm + SM_TILE_F;
    float* s_xl   = sm + SM_TILE_F + SM_ATT_F;

    int blk = blockIdx.x;
    int bl = blk / CHUNKS, chunk = blk - bl * CHUNKS;
    int b = bl / Ll, l = bl - b * Ll;
    int tid = threadIdx.x;

    const float* xh_bl   = xh_g + (size_t)bl * Tt * DF + chunk * DC * Ff;
    const float* att_src = (const float*)g_att2 + (size_t)bl * Tt * Cc * 2;
    const float* xl_src  = xl_g + (size_t)bl * DF + chunk * DC * Ff;

    for (int i = tid; i < N_CP16; i += 256) {
        const float* src;
        unsigned dst;
        if (i < SM_TILE_F / 4) {
            int row = i / (DC * Ff / 4);              // /48
            int col = (i - row * (DC * Ff / 4)) * 4;
            src = xh_bl + (size_t)row * DF + col;
            dst = (unsigned)__cvta_generic_to_shared(s_tile + row * (DC * Ff) + col);
        } else if (i < (SM_TILE_F + SM_ATT_F) / 4) {
            int j = (i - SM_TILE_F / 4) * 4;
            src = att_src + j;
            dst = (unsigned)__cvta_generic_to_shared(s_att + j);
        } else {
            int j = (i - (SM_TILE_F + SM_ATT_F) / 4) * 4;
            src = xl_src + j;
            dst = (unsigned)__cvta_generic_to_shared(s_xl + j);
        }
        CP16(dst, src);
    }
    asm volatile("cp.async.commit_group;");
    asm volatile("cp.async.wait_group 0;");
    __syncthreads();

    int wid = tid >> 5, c = tid & 31;
    int dw = wid * 8;                      // 8 d per warp

    unsigned long long H[12];
    #pragma unroll
    for (int k = 0; k < 12; k++) H[k] = 0ull;

    const unsigned long long* ap = (const unsigned long long*)s_att + c;
    const float* tp = s_tile + dw * Ff;

    #pragma unroll 6
    for (int t = 0; t < Tt; t++) {
        unsigned long long av = ap[t * Cc];
        const ulonglong2* p = (const ulonglong2*)(tp + t * (DC * Ff));
        #pragma unroll
        for (int g = 0; g < 2; g++) {
            ulonglong2 x0 = p[3 * g + 0];
            ulonglong2 x1 = p[3 * g + 1];
            ulonglong2 x2 = p[3 * g + 2];
            FFMA2(H[6 * g + 0], x0.x, av);
            FFMA2(H[6 * g + 1], x0.y, av);
            FFMA2(H[6 * g + 2], x1.x, av);
            FFMA2(H[6 * g + 3], x1.y, av);
            FFMA2(H[6 * g + 4], x2.x, av);
            FFMA2(H[6 * g + 5], x2.y, av);
        }
    }

    float wc0 = Wc[c * 3 + 0], wc1 = Wc[c * 3 + 1], wc2 = Wc[c * 3 + 2], bcc = bc[c];
    float wq0 = Wq[c * 3 + 0], wq1 = Wq[c * 3 + 1], wq2 = Wq[c * 3 + 2], bqc = bq[c];

    float* op = out + (((size_t)b * Cc + c) * Ll + l) * Dd + chunk * DC + dw;

    #pragma unroll
    for (int g = 0; g < 2; g++) {
        U2F k0, k1, k2, k3, k4, k5;
        k0.u = H[6 * g + 0]; k1.u = H[6 * g + 1]; k2.u = H[6 * g + 2];
        k3.u = H[6 * g + 3]; k4.u = H[6 * g + 4]; k5.u = H[6 * g + 5];
        float ov0 = fmaf(wc2, k1.f.x, fmaf(wc1, k0.f.y, fmaf(wc0, k0.f.x, bcc)));
        float ov1 = fmaf(wc2, k2.f.y, fmaf(wc1, k2.f.x, fmaf(wc0, k1.f.y, bcc)));
        float ov2 = fmaf(wc2, k4.f.x, fmaf(wc1, k3.f.y, fmaf(wc0, k3.f.x, bcc)));
        float ov3 = fmaf(wc2, k5.f.y, fmaf(wc1, k5.f.x, fmaf(wc0, k4.f.y, bcc)));

        const float* xp = s_xl + (dw + 4 * g) * Ff;
        float q0 = fmaf(wq2, xp[2],  fmaf(wq1, xp[1],  fmaf(wq0, xp[0], bqc)));
        float q1 = fmaf(wq2, xp[5],  fmaf(wq1, xp[4],  fmaf(wq0, xp[3], bqc)));
        float q2 = fmaf(wq2, xp[8],  fmaf(wq1, xp[7],  fmaf(wq0, xp[6], bqc)));
        float q3 = fmaf(wq2, xp[11], fmaf(wq1, xp[10], fmaf(wq0, xp[9], bqc)));

        float4 res = make_float4(q0 + ov0, q1 + ov1, q2 + ov2, q3 + ov3);
        *(float4*)(op + 4 * g) = res;
    }
}

extern "C" void kernel_launch(void* const* d_in, const int* in_sizes, int n_in,
                              void* d_out, int out_size)
{
    const float* xl = (const float*)d_in[0];
    const float* xh = (const float*)d_in[1];
    const float* Wq = (const float*)d_in[2];
    const float* bq = (const float*)d_in[3];
    const float* Wm = (const float*)d_in[4];
    const float* bm = (const float*)d_in[5];
    const float* Wc = (const float*)d_in[6];
    const float* bc = (const float*)d_in[7];
    float* out = (float*)d_out;

    static int attr_set = 0;
    if (!attr_set) {
        cudaFuncSetAttribute(k_gram, cudaFuncAttributeMaxDynamicSharedMemorySize,
                             GRAM_SMEM_F * 4);
        cudaFuncSetAttribute(k_out, cudaFuncAttributeMaxDynamicSharedMemorySize,
                             (SM_TILE_F + SM_ATT_F + SM_XL_F) * 4);
        attr_set = 1;
    }

    k_gram<<<dim3(Tt / TG, BL), 256, GRAM_SMEM_F * 4>>>(xh, xl);
    k_score<<<BL, 256>>>(xl, Wq, bq, Wm, bm);
    k_out<<<BL * CHUNKS, 256, (SM_TILE_F + SM_ATT_F + SM_XL_F) * 4>>>(
        xl, xh, Wq, bq, Wc, bc, out);
}